// round 15
// baseline (speedup 1.0000x reference)
#include <cuda_runtime.h>
typedef unsigned int u32; typedef unsigned short u16;

#define SQ   2048
#define QT   64
#define KTL  64
#define NT   (SQ/KTL)
#define NTHR 256              // 8 warps: 0-3 MMA(+loads), 4-7 RNG
#define STRB 144              // smem row stride bytes (72 bf16: 64 + 8 pad)

// K/V ping-pong buffers; offsets within one buffer:
#define KHI  0
#define KLO  9216
#define VHI  18432
#define VLO  27648
#define BUFS 36864
#define QHI  73728
#define QLO  82944
#define BITS 92160            // 2 x 512 B keep-bit stages
#define SMEM_SZ 93184

#define T_SCALE 0.22542110013890053f   // (1/(8*0.8))*log2(e)
#define M_LOG2  17.312340490667560f    // 12*log2(e) fixed softmax max
#define KEEP_T  0xCCCCCE00u

__device__ u32 g_one = 1;     // opaque 1: blocks ptxas strength-reduction

static __device__ __forceinline__ u32 smem_u32(const void* p){
    u32 a; asm("{ .reg .u64 t; cvta.to.shared.u64 t, %1; cvt.u32.u64 %0, t; }":"=r"(a):"l"(p)); return a;
}
static __device__ __forceinline__ float ex2f(float x){ float y; asm("ex2.approx.ftz.f32 %0,%1;":"=f"(y):"f"(x)); return y; }
static __device__ __forceinline__ u32 pack_bf16(float lo, float hi){
    u32 d; asm("cvt.rn.bf16x2.f32 %0, %1, %2;" : "=r"(d) : "f"(hi), "f"(lo)); return d;
}
static __device__ __forceinline__ float lo_f(u32 p){ return __uint_as_float(p<<16); }
static __device__ __forceinline__ float hi_f(u32 p){ return __uint_as_float(p & 0xffff0000u); }

// ---- port-balanced integer helpers (fma pipe via IMAD, opaque operands) ----
static __device__ __forceinline__ u32 madd(u32 a, u32 one, u32 b){
    u32 d; asm("mad.lo.s32 %0, %1, %2, %3;" : "=r"(d) : "r"(a), "r"(one), "r"(b)); return d;
}
#define MADDI(a, one, imm) ({ u32 _d; \
    asm("mad.lo.s32 %0, %1, %2, %3;" : "=r"(_d) : "r"(a), "r"(one), "n"(imm)); _d; })
// rotl(x,r) on the fma pipe: p == 2^r (opaque). 64-bit x*p splits into
// hi = x>>(32-r), lo = x<<r; their sum is the rotate.
static __device__ __forceinline__ u32 rot_imad(u32 x, u32 p){
    u32 t, y;
    asm("mul.lo.u32 %0, %1, %2;" : "=r"(t) : "r"(x), "r"(p));
    asm("mad.hi.u32 %0, %1, %2, %3;" : "=r"(y) : "r"(x), "r"(p), "r"(t));
    return y;
}

// threefry2x32, key (0,42), counter (0,n) -> out0^out1. Bit-identical to the
// R11-validated fused-key version; adds on IMAD, 6/20 rotates on IMAD pairs.
static __device__ __forceinline__ u32 threefry_bits(u32 n, u32 one, u32 p26, u32 p6){
    u32 x0 = 0u, x1 = MADDI(n, one, 42);
#define TFR(r) { x0 = madd(x1, one, x0); x1 = __funnelshift_l(x1,x1,(r)) ^ x0; }
#define TFM(p) { x0 = madd(x1, one, x0); x1 = rot_imad(x1,(p)) ^ x0; }
#define TFF(r,K,C) { u32 t1 = MADDI(x1, one, (int)(C)); x0 = MADDI(x0, one, (int)(K)); \
                     x0 = madd(t1, one, x0); x1 = __funnelshift_l(t1,t1,(r)) ^ x0; }
    TFR(13) TFR(15) TFM(p26) TFM(p6)
    TFF(17, 42u,          0x1BD11BF1u)
    TFR(29) TFR(16) TFR(24)
    TFF(13, 0x1BD11BF0u,  2u)
    TFR(15) TFM(p26) TFM(p6)
    TFF(17, 0u,           45u)
    TFR(29) TFR(16) TFR(24)
    TFF(13, 42u,          0x1BD11BF4u)
    TFR(15) TFM(p26) TFM(p6)
#undef TFR
#undef TFM
#undef TFF
    return (MADDI(x0, one, (int)0x1BD11BF0)) ^ (MADDI(x1, one, 5));
}

static __device__ __forceinline__ void ldm4(u32* r, u32 a){
    asm volatile("ldmatrix.sync.aligned.m8n8.x4.shared.b16 {%0,%1,%2,%3},[%4];"
        : "=r"(r[0]),"=r"(r[1]),"=r"(r[2]),"=r"(r[3]) : "r"(a));
}
static __device__ __forceinline__ void ldm4t(u32* r, u32 a){
    asm volatile("ldmatrix.sync.aligned.m8n8.x4.trans.shared.b16 {%0,%1,%2,%3},[%4];"
        : "=r"(r[0]),"=r"(r[1]),"=r"(r[2]),"=r"(r[3]) : "r"(a));
}
static __device__ __forceinline__ void mma(float* c, const u32* a, const u32* b){
    asm volatile("mma.sync.aligned.m16n8k16.row.col.f32.bf16.bf16.f32 "
        "{%0,%1,%2,%3},{%4,%5,%6,%7},{%8,%9},{%0,%1,%2,%3};"
        : "+f"(c[0]),"+f"(c[1]),"+f"(c[2]),"+f"(c[3])
        : "r"(a[0]),"r"(a[1]),"r"(a[2]),"r"(a[3]),"r"(b[0]),"r"(b[1]));
}
static __device__ __forceinline__ void st_hilo(char* bh, char* bl, float4 v){
    u32 h01 = pack_bf16(v.x, v.y), h23 = pack_bf16(v.z, v.w);
    u32 l01 = pack_bf16(v.x - lo_f(h01), v.y - hi_f(h01));
    u32 l23 = pack_bf16(v.z - lo_f(h23), v.w - hi_f(h23));
    *(uint2*)bh = make_uint2(h01, h23);
    *(uint2*)bl = make_uint2(l01, l23);
}
static __device__ __forceinline__ float epi(float c, u32 keepbit, u32 mb){
    float tt = fmaf(c, T_SCALE, -M_LOG2);
    if (mb) tt = -1e30f;               // masked -> -inf
    if (!keepbit) tt = -M_LOG2;        // dropped -> score 0
    return ex2f(tt);
}

// MMA warps (128 thr): load + bf16-split one 64x64 K,V tile into buffer boff.
static __device__ __forceinline__ void load_kv(char* smem, u32 boff,
                                               const float* Kp, const float* Vp, int tid){
    #pragma unroll
    for (int j=0;j<8;j+=2){
        int e0 = tid + j*128, e1 = tid + (j+1)*128;
        float4 ka = ((const float4*)Kp)[e0];
        float4 kb = ((const float4*)Kp)[e1];
        float4 va = ((const float4*)Vp)[e0];
        float4 vb = ((const float4*)Vp)[e1];
        int r0 = e0>>4, c0 = (e0&15)*4, r1 = e1>>4, c1 = (e1&15)*4;
        st_hilo(smem+boff+KHI+r0*STRB+c0*2, smem+boff+KLO+r0*STRB+c0*2, ka);
        st_hilo(smem+boff+VHI+r0*STRB+c0*2, smem+boff+VLO+r0*STRB+c0*2, va);
        st_hilo(smem+boff+KHI+r1*STRB+c1*2, smem+boff+KLO+r1*STRB+c1*2, kb);
        st_hilo(smem+boff+VHI+r1*STRB+c1*2, smem+boff+VLO+r1*STRB+c1*2, vb);
    }
}

// RNG warps: keep-bits for one 64x64 tile; warp covers rows [wrow0, wrow0+16).
// 4 independent threefry chains in flight; ballot packs 32 bits -> 1 word.
static __device__ __forceinline__ void rng_tile(u32* buf, u32 nrow0, int wrow0, int lane, int k0,
                                                u32 one, u32 p26, u32 p6){
    u32 nb = nrow0 + (u32)wrow0*SQ + (u32)k0 + (u32)lane;
    #pragma unroll 1
    for (int i=0;i<16;i+=2){
        u32 na = nb + (u32)i*(u32)SQ;
        u32 c0 = threefry_bits(na,                 one, p26, p6);
        u32 c1 = threefry_bits(na + 32u,           one, p26, p6);
        u32 c2 = threefry_bits(na + (u32)SQ,       one, p26, p6);
        u32 c3 = threefry_bits(na + (u32)SQ + 32u, one, p26, p6);
        u32 k0a = __ballot_sync(0xffffffffu, c0 < KEEP_T);
        u32 k0b = __ballot_sync(0xffffffffu, c1 < KEEP_T);
        u32 k1a = __ballot_sync(0xffffffffu, c2 < KEEP_T);
        u32 k1b = __ballot_sync(0xffffffffu, c3 < KEEP_T);
        if (lane == 0){
            *(uint2*)&buf[(wrow0+i)*2]   = make_uint2(k0a, k0b);
            *(uint2*)&buf[(wrow0+i+1)*2] = make_uint2(k1a, k1b);
        }
    }
}

__global__ void __launch_bounds__(NTHR, 2)
attn_ws(const float* __restrict__ Kg, const float* __restrict__ Vg,
        const float* __restrict__ Qg, const unsigned char* __restrict__ Mg,
        float* __restrict__ Og)
{
    extern __shared__ __align__(128) char smem[];
    const int tid = threadIdx.x, w = tid>>5, lane = tid&31;
    const int b = blockIdx.y, q0 = blockIdx.x*QT;
    const int r0 = (w&3)*16 + (lane>>2);   // MMA-warp row base
    const int c2 = (lane&3)*2;
    const u32 sbase = smem_u32(smem);
    u32* bits0 = (u32*)(smem + BITS);
    u32* bits1 = bits0 + 128;
    const u32 nrow0 = (u32)((b*SQ + q0)*SQ);
    const u32 one = *(volatile u32*)&g_one;   // opaque 1
    const u32 p26 = one << 26, p6 = one << 6; // opaque 2^26, 2^6

    const float* Kbase = Kg + ((size_t)b*SQ)*64;
    const float* Vbase = Vg + ((size_t)b*SQ)*64;

    // ---- prologue: MMA warps stage Q + KV(0); RNG warps do bits(0) ----
    if (w < 4) {
        const float* Qp = Qg + ((size_t)(b*SQ + q0))*64;
        #pragma unroll
        for (int j=0;j<8;j++){
            int e = tid + j*128;
            float4 v = ((const float4*)Qp)[e];
            int row = e>>4, k4 = (e&15)*4;
            st_hilo(smem + QHI + row*STRB + k4*2, smem + QLO + row*STRB + k4*2, v);
        }
        load_kv(smem, 0u, Kbase, Vbase, tid);
    } else {
        rng_tile(bits0, nrow0, (w-4)*16, lane, 0, one, p26, p6);
    }
    __syncthreads();

    float O[8][4];
    #pragma unroll
    for (int j=0;j<8;j++){ O[j][0]=0.f;O[j][1]=0.f;O[j][2]=0.f;O[j][3]=0.f; }
    float l0 = 0.f, l8 = 0.f;

    const unsigned char* m0 = Mg + ((size_t)(b*SQ + q0 + r0))*SQ;
    const u32 qa = sbase + (u32)(((w&3)*16 + ((lane>>3)&1)*8 + (lane&7))*STRB + ((lane>>4)&1)*16);
    const u32 kb = sbase + (u32)(((((lane>>4)&1)*8) + (lane&7))*STRB + ((lane>>3)&1)*16);
    const u32 vb = sbase + (u32)(((((lane>>3)&1)*8) + (lane&7))*STRB + ((lane>>4)&1)*16);

    for (int t=0;t<NT;t++){
        const int k0 = t*KTL;
        const u32 boff = (u32)(t&1)*BUFS;

        if (w >= 4) {
            // ---- RNG warps: bits(t+1) into the other stage ----
            if (t+1 < NT)
                rng_tile((t&1) ? bits0 : bits1, nrow0, (w-4)*16, lane, k0 + KTL, one, p26, p6);
            __syncthreads();
            continue;
        }

        // ================= MMA warps =================
        // ---- prefetch K,V(t+1) into the other buffer (overlaps compute) ----
        if (t+1 < NT)
            load_kv(smem, (u32)((t+1)&1)*BUFS, Kbase + (size_t)(k0+KTL)*64,
                    Vbase + (size_t)(k0+KTL)*64, tid);

        // ---- QK^T: 3-term bf16 (QhKh + QlKh + QhKl) ----
        float C[8][4];
        #pragma unroll
        for (int j=0;j<8;j++){ C[j][0]=0.f;C[j][1]=0.f;C[j][2]=0.f;C[j][3]=0.f; }
        #pragma unroll
        for (int s=0;s<4;s++){
            u32 qh[4], ql[4];
            ldm4(qh, qa + QHI + 32*s);
            ldm4(ql, qa + QLO + 32*s);
            #pragma unroll
            for (int jp=0;jp<4;jp++){
                u32 bh[4], bl[4];
                ldm4(bh, kb + boff + KHI + (u32)(jp*16*STRB + 32*s));
                ldm4(bl, kb + boff + KLO + (u32)(jp*16*STRB + 32*s));
                mma(C[2*jp],   qh, bh+0);  mma(C[2*jp+1], qh, bh+2);
                mma(C[2*jp],   ql, bh+0);  mma(C[2*jp+1], ql, bh+2);
                mma(C[2*jp],   qh, bl+0);  mma(C[2*jp+1], qh, bl+2);
            }
        }

        // ---- epilogue: precomputed keep-bits + mask + exp2; pack P frags ----
        const u32* bw = (t&1) ? bits1 : bits0;
        uint2 w0 = *(const uint2*)&bw[r0*2];
        uint2 w8 = *(const uint2*)&bw[(r0+8)*2];
        u32 Ph[4][4], Pl[4][4];
        #pragma unroll
        for (int j=0;j<8;j++){
            const int pos = c2 + (8*j)%32;
            const u32 kw0 = (j<4) ? w0.x : w0.y;
            const u32 kw8 = (j<4) ? w8.x : w8.y;
            u16 mw0 = *(const u16*)(m0 + k0 + 8*j + c2);
            u16 mw8 = *(const u16*)(m0 + 8*SQ + k0 + 8*j + c2);
            float p0 = epi(C[j][0], (kw0>>pos)&1u,     mw0 & 0xffu);
            float p1 = epi(C[j][1], (kw0>>(pos+1))&1u, mw0 >> 8);
            float p2 = epi(C[j][2], (kw8>>pos)&1u,     mw8 & 0xffu);
            float p3 = epi(C[j][3], (kw8>>(pos+1))&1u, mw8 >> 8);
            l0 += p0 + p1;  l8 += p2 + p3;
            u32 h01 = pack_bf16(p0, p1), h23 = pack_bf16(p2, p3);
            u32 lo01 = pack_bf16(p0 - lo_f(h01), p1 - hi_f(h01));
            u32 lo23 = pack_bf16(p2 - lo_f(h23), p3 - hi_f(h23));
            int s = j>>1, o = (j&1)*2;
            Ph[s][o] = h01; Ph[s][o+1] = h23;
            Pl[s][o] = lo01; Pl[s][o+1] = lo23;
        }

        // ---- AV: 3-term bf16 (PhVh + PlVh + PhVl), O accumulates ----
        #pragma unroll
        for (int s=0;s<4;s++){
            #pragma unroll
            for (int jp=0;jp<4;jp++){
                u32 bh[4], bl[4];
                ldm4t(bh, vb + boff + VHI + (u32)(s*16*STRB + jp*32));
                ldm4t(bl, vb + boff + VLO + (u32)(s*16*STRB + jp*32));
                mma(O[2*jp],   Ph[s], bh+0);  mma(O[2*jp+1], Ph[s], bh+2);
                mma(O[2*jp],   Pl[s], bh+0);  mma(O[2*jp+1], Pl[s], bh+2);
                mma(O[2*jp],   Ph[s], bl+0);  mma(O[2*jp+1], Ph[s], bl+2);
            }
        }
        __syncthreads();   // seals: buf(t+1)+bits(t+1) writes, buf/bits(t) reads
    }

    // ---- finalize (MMA warps): reduce l across quad lanes, normalize, store ----
    if (w < 4) {
        l0 += __shfl_xor_sync(0xffffffffu, l0, 1);
        l0 += __shfl_xor_sync(0xffffffffu, l0, 2);
        l8 += __shfl_xor_sync(0xffffffffu, l8, 1);
        l8 += __shfl_xor_sync(0xffffffffu, l8, 2);
        float i0 = 1.0f / l0, i8 = 1.0f / l8;
        float* o0 = Og + ((size_t)(b*SQ + q0 + r0))*64;
        #pragma unroll
        for (int j=0;j<8;j++){
            *(float2*)(o0 + 8*j + c2)       = make_float2(O[j][0]*i0, O[j][1]*i0);
            *(float2*)(o0 + 512 + 8*j + c2) = make_float2(O[j][2]*i8, O[j][3]*i8);
        }
    }
}

extern "C" void kernel_launch(void* const* d_in, const int* in_sizes, int n_in,
                              void* d_out, int out_size) {
    const float* K = (const float*)d_in[0];
    const float* V = (const float*)d_in[1];
    const float* Q = (const float*)d_in[2];
    const unsigned char* mask = (const unsigned char*)d_in[3];
    float* out = (float*)d_out;
    cudaFuncSetAttribute(attn_ws, cudaFuncAttributeMaxDynamicSharedMemorySize, SMEM_SZ);
    dim3 grid(SQ/QT, 32);
    attn_ws<<<grid, NTHR, SMEM_SZ>>>(K, V, Q, mask, out);
}

// round 16
// speedup vs baseline: 1.2236x; 1.2236x over previous
#include <cuda_runtime.h>
typedef unsigned int u32; typedef unsigned short u16;

#define SQ   2048
#define QT   64
#define KTL  64
#define NT   (SQ/KTL)
#define NTHR 256              // 8 warps: 0-3 RNG (low prio), 4-7 MMA+loads (high prio)
#define STRB 144              // smem row stride bytes (72 bf16: 64 + 8 pad)

// K/V ping-pong buffers; offsets within one buffer:
#define KHI  0
#define KLO  9216
#define VHI  18432
#define VLO  27648
#define BUFS 36864
#define QHI  73728
#define QLO  82944
#define BITS 92160            // 2 x 512 B keep-bit stages
#define SMEM_SZ 93184

#define T_SCALE 0.22542110013890053f   // (1/(8*0.8))*log2(e)
#define M_LOG2  17.312340490667560f    // 12*log2(e) fixed softmax max
#define KEEP_T  0xCCCCCE00u

static __device__ __forceinline__ u32 smem_u32(const void* p){
    u32 a; asm("{ .reg .u64 t; cvta.to.shared.u64 t, %1; cvt.u32.u64 %0, t; }":"=r"(a):"l"(p)); return a;
}
static __device__ __forceinline__ float ex2f(float x){ float y; asm("ex2.approx.ftz.f32 %0,%1;":"=f"(y):"f"(x)); return y; }
static __device__ __forceinline__ u32 pack_bf16(float lo, float hi){
    u32 d; asm("cvt.rn.bf16x2.f32 %0, %1, %2;" : "=r"(d) : "f"(hi), "f"(lo)); return d;
}
static __device__ __forceinline__ float lo_f(u32 p){ return __uint_as_float(p<<16); }
static __device__ __forceinline__ float hi_f(u32 p){ return __uint_as_float(p & 0xffff0000u); }

// threefry2x32, key (0,42), counter (0,n) -> out0^out1 (bit-exact since R1;
// plain encoding — the R10-measured best)
static __device__ __forceinline__ u32 threefry_bits(u32 n){
    u32 x0 = 0u, x1 = n + 42u;
#define TF_R(r) { x0 += x1; x1 = __funnelshift_l(x1,x1,(r)); x1 ^= x0; }
    TF_R(13) TF_R(15) TF_R(26) TF_R(6)
    x0 += 42u;         x1 += 0x1BD11BF0u + 1u;
    TF_R(17) TF_R(29) TF_R(16) TF_R(24)
    x0 += 0x1BD11BF0u; x1 += 0u + 2u;
    TF_R(13) TF_R(15) TF_R(26) TF_R(6)
    x0 += 0u;          x1 += 42u + 3u;
    TF_R(17) TF_R(29) TF_R(16) TF_R(24)
    x0 += 42u;         x1 += 0x1BD11BF0u + 4u;
    TF_R(13) TF_R(15) TF_R(26) TF_R(6)
    x0 += 0x1BD11BF0u; x1 += 0u + 5u;
#undef TF_R
    return x0 ^ x1;
}

static __device__ __forceinline__ void ldm4(u32* r, u32 a){
    asm volatile("ldmatrix.sync.aligned.m8n8.x4.shared.b16 {%0,%1,%2,%3},[%4];"
        : "=r"(r[0]),"=r"(r[1]),"=r"(r[2]),"=r"(r[3]) : "r"(a));
}
static __device__ __forceinline__ void ldm4t(u32* r, u32 a){
    asm volatile("ldmatrix.sync.aligned.m8n8.x4.trans.shared.b16 {%0,%1,%2,%3},[%4];"
        : "=r"(r[0]),"=r"(r[1]),"=r"(r[2]),"=r"(r[3]) : "r"(a));
}
static __device__ __forceinline__ void mma(float* c, const u32* a, const u32* b){
    asm volatile("mma.sync.aligned.m16n8k16.row.col.f32.bf16.bf16.f32 "
        "{%0,%1,%2,%3},{%4,%5,%6,%7},{%8,%9},{%0,%1,%2,%3};"
        : "+f"(c[0]),"+f"(c[1]),"+f"(c[2]),"+f"(c[3])
        : "r"(a[0]),"r"(a[1]),"r"(a[2]),"r"(a[3]),"r"(b[0]),"r"(b[1]));
}
static __device__ __forceinline__ void st_hilo(char* bh, char* bl, float4 v){
    u32 h01 = pack_bf16(v.x, v.y), h23 = pack_bf16(v.z, v.w);
    u32 l01 = pack_bf16(v.x - lo_f(h01), v.y - hi_f(h01));
    u32 l23 = pack_bf16(v.z - lo_f(h23), v.w - hi_f(h23));
    *(uint2*)bh = make_uint2(h01, h23);
    *(uint2*)bl = make_uint2(l01, l23);
}
static __device__ __forceinline__ float epi(float c, u32 keepbit, u32 mb){
    float tt = fmaf(c, T_SCALE, -M_LOG2);
    if (mb) tt = -1e30f;               // masked -> -inf
    if (!keepbit) tt = -M_LOG2;        // dropped -> score 0
    return ex2f(tt);
}

// MMA warps (128 thr, mtid in 0..127): load + bf16-split one 64x64 K,V tile.
static __device__ __forceinline__ void load_kv(char* smem, u32 boff,
                                               const float* Kp, const float* Vp, int mtid){
    #pragma unroll
    for (int j=0;j<8;j+=2){
        int e0 = mtid + j*128, e1 = mtid + (j+1)*128;
        float4 ka = ((const float4*)Kp)[e0];
        float4 kb = ((const float4*)Kp)[e1];
        float4 va = ((const float4*)Vp)[e0];
        float4 vb = ((const float4*)Vp)[e1];
        int r0 = e0>>4, c0 = (e0&15)*4, r1 = e1>>4, c1 = (e1&15)*4;
        st_hilo(smem+boff+KHI+r0*STRB+c0*2, smem+boff+KLO+r0*STRB+c0*2, ka);
        st_hilo(smem+boff+VHI+r0*STRB+c0*2, smem+boff+VLO+r0*STRB+c0*2, va);
        st_hilo(smem+boff+KHI+r1*STRB+c1*2, smem+boff+KLO+r1*STRB+c1*2, kb);
        st_hilo(smem+boff+VHI+r1*STRB+c1*2, smem+boff+VLO+r1*STRB+c1*2, vb);
    }
}

// RNG warps: keep-bits for one 64x64 tile; warp covers rows [wrow0, wrow0+16).
// 4 independent threefry chains in flight; ballot packs 32 bits -> 1 word.
static __device__ __forceinline__ void rng_tile(u32* buf, u32 nrow0, int wrow0, int lane, int k0){
    u32 nb = nrow0 + (u32)wrow0*SQ + (u32)k0 + (u32)lane;
    #pragma unroll 1
    for (int i=0;i<16;i+=2){
        u32 na = nb + (u32)i*(u32)SQ;
        u32 c0 = threefry_bits(na);
        u32 c1 = threefry_bits(na + 32u);
        u32 c2 = threefry_bits(na + (u32)SQ);
        u32 c3 = threefry_bits(na + (u32)SQ + 32u);
        u32 k0a = __ballot_sync(0xffffffffu, c0 < KEEP_T);
        u32 k0b = __ballot_sync(0xffffffffu, c1 < KEEP_T);
        u32 k1a = __ballot_sync(0xffffffffu, c2 < KEEP_T);
        u32 k1b = __ballot_sync(0xffffffffu, c3 < KEEP_T);
        if (lane == 0){
            *(uint2*)&buf[(wrow0+i)*2]   = make_uint2(k0a, k0b);
            *(uint2*)&buf[(wrow0+i+1)*2] = make_uint2(k1a, k1b);
        }
    }
}

__global__ void __launch_bounds__(NTHR, 2)
attn_ws(const float* __restrict__ Kg, const float* __restrict__ Vg,
        const float* __restrict__ Qg, const unsigned char* __restrict__ Mg,
        float* __restrict__ Og)
{
    extern __shared__ __align__(128) char smem[];
    const int tid = threadIdx.x, w = tid>>5, lane = tid&31;
    const int b = blockIdx.y, q0 = blockIdx.x*QT;
    const int mtid = tid & 127;            // MMA-group-local tid (for w>=4)
    const int r0 = (w&3)*16 + (lane>>2);   // MMA-warp row base
    const int c2 = (lane&3)*2;
    const u32 sbase = smem_u32(smem);
    u32* bits0 = (u32*)(smem + BITS);
    u32* bits1 = bits0 + 128;
    const u32 nrow0 = (u32)((b*SQ + q0)*SQ);

    const float* Kbase = Kg + ((size_t)b*SQ)*64;
    const float* Vbase = Vg + ((size_t)b*SQ)*64;

    // ---- prologue: MMA warps (w4-7, HIGH arbiter priority) stage Q + KV(0);
    //      RNG warps (w0-3, low priority) do bits(0) ----
    if (w >= 4) {
        const float* Qp = Qg + ((size_t)(b*SQ + q0))*64;
        #pragma unroll
        for (int j=0;j<8;j++){
            int e = mtid + j*128;
            float4 v = ((const float4*)Qp)[e];
            int row = e>>4, k4 = (e&15)*4;
            st_hilo(smem + QHI + row*STRB + k4*2, smem + QLO + row*STRB + k4*2, v);
        }
        load_kv(smem, 0u, Kbase, Vbase, mtid);
    } else {
        rng_tile(bits0, nrow0, w*16, lane, 0);
    }
    __syncthreads();

    float O[8][4];
    #pragma unroll
    for (int j=0;j<8;j++){ O[j][0]=0.f;O[j][1]=0.f;O[j][2]=0.f;O[j][3]=0.f; }
    float l0 = 0.f, l8 = 0.f;

    const unsigned char* m0 = Mg + ((size_t)(b*SQ + q0 + r0))*SQ;
    const u32 qa = sbase + (u32)(((w&3)*16 + ((lane>>3)&1)*8 + (lane&7))*STRB + ((lane>>4)&1)*16);
    const u32 kb = sbase + (u32)(((((lane>>4)&1)*8) + (lane&7))*STRB + ((lane>>3)&1)*16);
    const u32 vb = sbase + (u32)(((((lane>>3)&1)*8) + (lane&7))*STRB + ((lane>>4)&1)*16);

    for (int t=0;t<NT;t++){
        const int k0 = t*KTL;
        const u32 boff = (u32)(t&1)*BUFS;

        if (w < 4) {
            // ---- RNG warps: bits(t+1) into the other stage ----
            if (t+1 < NT)
                rng_tile((t&1) ? bits0 : bits1, nrow0, w*16, lane, k0 + KTL);
            __syncthreads();
            continue;
        }

        // ================= MMA warps (high priority) =================
        // ---- prefetch K,V(t+1) into the other buffer (overlaps compute) ----
        if (t+1 < NT)
            load_kv(smem, (u32)((t+1)&1)*BUFS, Kbase + (size_t)(k0+KTL)*64,
                    Vbase + (size_t)(k0+KTL)*64, mtid);

        // ---- QK^T: 3-term bf16 (QhKh + QlKh + QhKl) ----
        float C[8][4];
        #pragma unroll
        for (int j=0;j<8;j++){ C[j][0]=0.f;C[j][1]=0.f;C[j][2]=0.f;C[j][3]=0.f; }
        #pragma unroll
        for (int s=0;s<4;s++){
            u32 qh[4], ql[4];
            ldm4(qh, qa + QHI + 32*s);
            ldm4(ql, qa + QLO + 32*s);
            #pragma unroll
            for (int jp=0;jp<4;jp++){
                u32 bh[4], bl[4];
                ldm4(bh, kb + boff + KHI + (u32)(jp*16*STRB + 32*s));
                ldm4(bl, kb + boff + KLO + (u32)(jp*16*STRB + 32*s));
                mma(C[2*jp],   qh, bh+0);  mma(C[2*jp+1], qh, bh+2);
                mma(C[2*jp],   ql, bh+0);  mma(C[2*jp+1], ql, bh+2);
                mma(C[2*jp],   qh, bl+0);  mma(C[2*jp+1], qh, bl+2);
            }
        }

        // ---- epilogue: precomputed keep-bits + mask + exp2; pack P frags ----
        const u32* bw = (t&1) ? bits1 : bits0;
        uint2 w0 = *(const uint2*)&bw[r0*2];
        uint2 w8 = *(const uint2*)&bw[(r0+8)*2];
        u32 Ph[4][4], Pl[4][4];
        #pragma unroll
        for (int j=0;j<8;j++){
            const int pos = c2 + (8*j)%32;
            const u32 kw0 = (j<4) ? w0.x : w0.y;
            const u32 kw8 = (j<4) ? w8.x : w8.y;
            u16 mw0 = *(const u16*)(m0 + k0 + 8*j + c2);
            u16 mw8 = *(const u16*)(m0 + 8*SQ + k0 + 8*j + c2);
            float p0 = epi(C[j][0], (kw0>>pos)&1u,     mw0 & 0xffu);
            float p1 = epi(C[j][1], (kw0>>(pos+1))&1u, mw0 >> 8);
            float p2 = epi(C[j][2], (kw8>>pos)&1u,     mw8 & 0xffu);
            float p3 = epi(C[j][3], (kw8>>(pos+1))&1u, mw8 >> 8);
            l0 += p0 + p1;  l8 += p2 + p3;
            u32 h01 = pack_bf16(p0, p1), h23 = pack_bf16(p2, p3);
            u32 lo01 = pack_bf16(p0 - lo_f(h01), p1 - hi_f(h01));
            u32 lo23 = pack_bf16(p2 - lo_f(h23), p3 - hi_f(h23));
            int s = j>>1, o = (j&1)*2;
            Ph[s][o] = h01; Ph[s][o+1] = h23;
            Pl[s][o] = lo01; Pl[s][o+1] = lo23;
        }

        // ---- AV: 3-term bf16 (PhVh + PlVh + PhVl), O accumulates ----
        #pragma unroll
        for (int s=0;s<4;s++){
            #pragma unroll
            for (int jp=0;jp<4;jp++){
                u32 bh[4], bl[4];
                ldm4t(bh, vb + boff + VHI + (u32)(s*16*STRB + jp*32));
                ldm4t(bl, vb + boff + VLO + (u32)(s*16*STRB + jp*32));
                mma(O[2*jp],   Ph[s], bh+0);  mma(O[2*jp+1], Ph[s], bh+2);
                mma(O[2*jp],   Pl[s], bh+0);  mma(O[2*jp+1], Pl[s], bh+2);
                mma(O[2*jp],   Ph[s], bl+0);  mma(O[2*jp+1], Ph[s], bl+2);
            }
        }
        __syncthreads();   // seals: buf(t+1)+bits(t+1) writes, buf/bits(t) reads
    }

    // ---- finalize (MMA warps): reduce l across quad lanes, normalize, store ----
    if (w >= 4) {
        l0 += __shfl_xor_sync(0xffffffffu, l0, 1);
        l0 += __shfl_xor_sync(0xffffffffu, l0, 2);
        l8 += __shfl_xor_sync(0xffffffffu, l8, 1);
        l8 += __shfl_xor_sync(0xffffffffu, l8, 2);
        float i0 = 1.0f / l0, i8 = 1.0f / l8;
        float* o0 = Og + ((size_t)(b*SQ + q0 + r0))*64;
        #pragma unroll
        for (int j=0;j<8;j++){
            *(float2*)(o0 + 8*j + c2)       = make_float2(O[j][0]*i0, O[j][1]*i0);
            *(float2*)(o0 + 512 + 8*j + c2) = make_float2(O[j][2]*i8, O[j][3]*i8);
        }
    }
}

extern "C" void kernel_launch(void* const* d_in, const int* in_sizes, int n_in,
                              void* d_out, int out_size) {
    const float* K = (const float*)d_in[0];
    const float* V = (const float*)d_in[1];
    const float* Q = (const float*)d_in[2];
    const unsigned char* mask = (const unsigned char*)d_in[3];
    float* out = (float*)d_out;
    cudaFuncSetAttribute(attn_ws, cudaFuncAttributeMaxDynamicSharedMemorySize, SMEM_SZ);
    dim3 grid(SQ/QT, 32);
    attn_ws<<<grid, NTHR, SMEM_SZ>>>(K, V, Q, mask, out);
}